// round 17
// baseline (speedup 1.0000x reference)
#include <cuda_runtime.h>

#define T_LEN  512
#define HH     50
#define G4     200
#define GB     16
#define NTHR   640     // 2 halves x 320 (10 warps each)
#define NCTA   128
#define HS     20
#define HBUF   (100 * HS)

// shared layout (float offsets)
#define OFF_W0T   0        // [50][200]  relayout: k*200 + c*8 + p*2 + e
#define OFF_WCT   10000    // [100][200] same
#define OFF_WIH0  30000    // [200] original gate order
#define OFF_B0    30200
#define OFF_B1    30400
#define OFF_HCAT  30600    // [2][100][20] double-buffered; cols 0-7 halfA, 8-15 halfB
#define OFF_XS    34600    // [512][16] full x staged once
#define SMEM_FLOATS 42792
#define SMEM_BYTES  (SMEM_FLOATS * 4)

typedef unsigned long long ull;

#define FFMA2(d, a, b) asm("fma.rn.f32x2 %0, %1, %2, %0;" : "+l"(d) : "l"(a), "l"(b))
#define ADDF2(d, a)    asm("add.rn.f32x2 %0, %0, %1;" : "+l"(d) : "l"(a))
#define UNPACK2(lo, hi, v) asm("mov.b64 {%0, %1}, %2;" : "=f"(lo), "=f"(hi) : "l"(v))
#define PACKDUP(d, s)  asm("mov.b64 %0, {%1, %1};" : "=l"(d) : "f"(s))

__device__ __forceinline__ ull shfl_xor_u64(ull v, int m) {
    unsigned lo, hi;
    asm("mov.b64 {%0, %1}, %2;" : "=r"(lo), "=r"(hi) : "l"(v));
    lo = __shfl_xor_sync(0xffffffffu, lo, m);
    hi = __shfl_xor_sync(0xffffffffu, hi, m);
    ull r;
    asm("mov.b64 %0, {%1, %2};" : "=l"(r) : "r"(lo), "r"(hi));
    return r;
}

__device__ __forceinline__ float sigf(float x) {
    return __fdividef(1.f, 1.f + __expf(-x));
}
__device__ __forceinline__ float tanh_fast(float x) {
    return fmaf(2.f, __fdividef(1.f, 1.f + __expf(-2.f * x)), -1.f);
}

extern __shared__ float sm[];

__global__ __launch_bounds__(NTHR, 1)
void lstm2_kernel(const float* __restrict__ x,
                  const float* __restrict__ Wih0, const float* __restrict__ Whh0,
                  const float* __restrict__ bih0, const float* __restrict__ bhh0,
                  const float* __restrict__ Wih1, const float* __restrict__ Whh1,
                  const float* __restrict__ bih1, const float* __restrict__ bhh1,
                  const float* __restrict__ Wfc,  const float* __restrict__ bfc,
                  float* __restrict__ out)
{
    const int tid = threadIdx.x;
    const int b0  = blockIdx.x * GB;

    // ---- stage weights: relayout [k][c][p*2+e] ----
    for (int i = tid; i < G4 * HH; i += NTHR) {
        int j = i / HH, k = i % HH;
        int p = j / 50, rm = j % 50, cc = rm >> 1, e = rm & 1;
        int dst = k * G4 + cc * 8 + p * 2 + e;
        sm[OFF_W0T + dst]            = Whh0[i];
        sm[OFF_WCT + dst]            = Wih1[i];
        sm[OFF_WCT + 50 * G4 + dst]  = Whh1[i];
    }
    for (int i = tid; i < G4; i += NTHR) {
        sm[OFF_WIH0 + i] = Wih0[i];
        sm[OFF_B0 + i]   = bih0[i] + bhh0[i];
        sm[OFF_B1 + i]   = bih1[i] + bhh1[i];
    }
    for (int i = tid; i < 2 * HBUF; i += NTHR) sm[OFF_HCAT + i] = 0.f;
    // stage ALL of x (coalesced gmem reads)
    for (int i = tid; i < GB * T_LEN; i += NTHR) {
        int b = i >> 9, tt = i & 511;
        sm[OFF_XS + tt * GB + b] = x[(b0 + b) * T_LEN + tt];
    }
    __syncthreads();

    // two independent halves of 320 threads (8 batch rows each)
    // per half: u 0..199 -> L1 (4 k-slices x 25 c x 2 bg), 200..299 -> L0
    // (2 k-slices x 25 c x 2 bg), 300..319 pad (compute garbage, never store)
    const int  half = (tid >= 320);
    const int  u    = tid - 320 * half;
    const bool isL1 = (u < 200);
    const bool isL0 = (u >= 200) && (u < 300);
    const int  v    = isL1 ? u : ((u - 200 < 100) ? (u - 200) : 99);
    const int  bg   = v & 1;
    const int  q    = isL1 ? ((v >> 1) & 3) : ((v >> 1) & 1);
    const int  c    = isL1 ? (v >> 3) : (v >> 2);
    const int  hcol = 8 * half;
    const int  xme  = isL1 ? (q & ~1) : (2 * q);
    const bool eswap = isL1 && (q & 1);
    const int  rdA  = isL1 ? 4 : 2;

    const float* wb = sm + (isL1 ? OFF_WCT : OFF_W0T) + 25 * q * G4 + 8 * c;
    const int hoA = 25 * q * HS + hcol + 4 * bg + xme;
    const int hoB = 25 * q * HS + hcol + 4 * bg + (2 ^ xme);

    const bool addBias = (q == 0);
    const bool addX    = isL0 && (q == 0);

    ull bp[4], w0p[4];
    {
        const float* bs = sm + (isL1 ? OFF_B1 : OFF_B0) + 2 * c;
        const float* ws = sm + OFF_WIH0 + 2 * c;
        #pragma unroll
        for (int p = 0; p < 4; ++p) {
            bp[p]  = *(const ull*)(bs + 50 * p);
            w0p[p] = *(const ull*)(ws + 50 * p);
        }
    }

    float cst[4];
    #pragma unroll
    for (int i = 0; i < 4; ++i) cst[i] = 0.f;

    const int hrow0 = (isL1 ? (HH + 2 * c) : (2 * c)) * HS;
    const int hrow1 = hrow0 + HS;

    for (int t = 0; t <= T_LEN; ++t) {
        const float* hc = sm + OFF_HCAT + (t & 1) * HBUF;

        // ================= fused matvec: gates0(t) + gates1(t-1) =========
        ull acc[4][4];
        #pragma unroll
        for (int j = 0; j < 4; ++j)
            #pragma unroll
            for (int p = 0; p < 4; ++p)
                acc[j][p] = addBias ? bp[p] : 0ull;

        if (addX) {   // L0 q==0: slot labels identity (xme==0)
            const float* xr = sm + OFF_XS + t * GB + hcol + 4 * bg;
            #pragma unroll
            for (int j = 0; j < 4; ++j) {
                ull xp; PACKDUP(xp, xr[j]);
                #pragma unroll
                for (int p = 0; p < 4; ++p) FFMA2(acc[j][p], w0p[p], xp);
            }
        }

        #pragma unroll 5
        for (int k = 0; k < 25; ++k) {
            const float* wr = wb + k * G4;
            ulonglong2 wA = *(const ulonglong2*)(wr);
            ulonglong2 wB = *(const ulonglong2*)(wr + 4);
            float2 vA = *(const float2*)(hc + hoA + k * HS);
            float2 vB = *(const float2*)(hc + hoB + k * HS);
            ull hp0, hp1, hp2, hp3;
            PACKDUP(hp0, vA.x); PACKDUP(hp1, vA.y);
            PACKDUP(hp2, vB.x); PACKDUP(hp3, vB.y);
            FFMA2(acc[0][0], wA.x, hp0); FFMA2(acc[0][1], wA.y, hp0);
            FFMA2(acc[0][2], wB.x, hp0); FFMA2(acc[0][3], wB.y, hp0);
            FFMA2(acc[1][0], wA.x, hp1); FFMA2(acc[1][1], wA.y, hp1);
            FFMA2(acc[1][2], wB.x, hp1); FFMA2(acc[1][3], wB.y, hp1);
            FFMA2(acc[2][0], wA.x, hp2); FFMA2(acc[2][1], wA.y, hp2);
            FFMA2(acc[2][2], wB.x, hp2); FFMA2(acc[2][3], wB.y, hp2);
            FFMA2(acc[3][0], wA.x, hp3); FFMA2(acc[3][1], wA.y, hp3);
            FFMA2(acc[3][2], wB.x, hp3); FFMA2(acc[3][3], wB.y, hp3);
        }

        // ============ in-warp k-reduction (XOR reduce-scatter) ==========
        // round A: fold slots {2,3} -> {0,1}; partner flips top q bit
        // (L1 lane-dist 4, L0/pad 2 — XOR distances never cross role regions)
        #pragma unroll
        for (int m = 0; m < 2; ++m)
            #pragma unroll
            for (int p = 0; p < 4; ++p) {
                ull o = shfl_xor_u64(acc[m + 2][p], rdA);
                ADDF2(acc[m][p], o);
            }
        // e-swap: L1 odd slices normalize slot labels
        #pragma unroll
        for (int p = 0; p < 4; ++p) {
            ull a = acc[0][p], b = acc[1][p];
            acc[0][p] = eswap ? b : a;
            acc[1][p] = eswap ? a : b;
        }
        // round B (adds L1-only): fold slot 1 -> 0; flips q low bit (dist 2)
        #pragma unroll
        for (int p = 0; p < 4; ++p) {
            ull o = shfl_xor_u64(acc[1][p], 2);
            if (isL1) ADDF2(acc[0][p], o);
        }

        // ================= elementwise (registers only) =================
        float* hw = sm + OFF_HCAT + ((t + 1) & 1) * HBUF;
        if (isL1 && t > 0) {
            // owns local batch 4bg+q, units 2c,2c+1
            float gi0, gi1, gf0, gf1, gg0, gg1, go0, go1;
            UNPACK2(gi0, gi1, acc[0][0]);
            UNPACK2(gf0, gf1, acc[0][1]);
            UNPACK2(gg0, gg1, acc[0][2]);
            UNPACK2(go0, go1, acc[0][3]);
            float c0 = fmaf(sigf(gf0), cst[0], sigf(gi0) * tanh_fast(gg0));
            float c1 = fmaf(sigf(gf1), cst[1], sigf(gi1) * tanh_fast(gg1));
            cst[0] = c0; cst[1] = c1;
            int boff = hcol + 4 * bg + q;
            hw[hrow0 + boff] = sigf(go0) * tanh_fast(c0);
            hw[hrow1 + boff] = sigf(go1) * tanh_fast(c1);
        }
        if (isL0 && t < T_LEN) {
            // owns local batches 4bg+2q, 4bg+2q+1 (slots 0,1)
            float h0[2], h1[2];
            #pragma unroll
            for (int s = 0; s < 2; ++s) {
                float gi0, gi1, gf0, gf1, gg0, gg1, go0, go1;
                UNPACK2(gi0, gi1, acc[s][0]);
                UNPACK2(gf0, gf1, acc[s][1]);
                UNPACK2(gg0, gg1, acc[s][2]);
                UNPACK2(go0, go1, acc[s][3]);
                float c0 = fmaf(sigf(gf0), cst[2 * s],     sigf(gi0) * tanh_fast(gg0));
                float c1 = fmaf(sigf(gf1), cst[2 * s + 1], sigf(gi1) * tanh_fast(gg1));
                cst[2 * s] = c0; cst[2 * s + 1] = c1;
                h0[s] = sigf(go0) * tanh_fast(c0);
                h1[s] = sigf(go1) * tanh_fast(c1);
            }
            int boff = hcol + 4 * bg + 2 * q;
            *(float2*)(hw + hrow0 + boff) = make_float2(h0[0], h0[1]);
            *(float2*)(hw + hrow1 + boff) = make_float2(h1[0], h1[1]);
        }

        // per-half barrier: the two halves run de-phased, hiding each
        // other's reduction/MUFU/barrier tails
        if (tid < 320) asm volatile("bar.sync 1, 320;" ::: "memory");
        else           asm volatile("bar.sync 2, 320;" ::: "memory");
    }

    __syncthreads();   // join halves before classifier

    // ================= final classifier on h2[T-1] =================
    const float* hf = sm + OFF_HCAT + ((T_LEN + 1) & 1) * HBUF;
    if (tid < GB * 2) {
        int bb = tid >> 1, cls = tid & 1;
        float acc2 = bfc[cls];
        #pragma unroll
        for (int k = 0; k < HH; ++k)
            acc2 = fmaf(Wfc[cls * HH + k], hf[(HH + k) * HS + bb], acc2);
        out[(b0 + bb) * 2 + cls] = acc2;
    }
}

extern "C" void kernel_launch(void* const* d_in, const int* in_sizes, int n_in,
                              void* d_out, int out_size)
{
    const float* x    = (const float*)d_in[0];
    const float* Wih0 = (const float*)d_in[1];
    const float* Whh0 = (const float*)d_in[2];
    const float* bih0 = (const float*)d_in[3];
    const float* bhh0 = (const float*)d_in[4];
    const float* Wih1 = (const float*)d_in[5];
    const float* Whh1 = (const float*)d_in[6];
    const float* bih1 = (const float*)d_in[7];
    const float* bhh1 = (const float*)d_in[8];
    const float* Wfc  = (const float*)d_in[9];
    const float* bfc  = (const float*)d_in[10];
    float* out = (float*)d_out;

    cudaFuncSetAttribute(lstm2_kernel,
                         cudaFuncAttributeMaxDynamicSharedMemorySize, SMEM_BYTES);
    lstm2_kernel<<<NCTA, NTHR, SMEM_BYTES>>>(
        x, Wih0, Whh0, bih0, bhh0, Wih1, Whh1, bih1, bhh1, Wfc, bfc, out);
}